// round 11
// baseline (speedup 1.0000x reference)
#include <cuda_runtime.h>
#include <cuda_bf16.h>
#include <cstdint>

#define BB 512
#define SS 336
#define INW 7
#define HH 512
#define TT 96
#define NCTA 128
#define GRP 32    // CTAs per independent group

typedef unsigned long long ull;
typedef __nv_bfloat16 bf16;

// ---------------- smem layout (bytes) ----------------
#define SM_BIAS0 0
#define SM_BIAS1 256
#define SM_XW    512
#define SM_XS    2560
#define SM_BUF   8192
#define OFF_AH   0
#define OFF_AL   18432
#define OFF_BH   36864
#define OFF_BL   46080
#define BUFSZ    55296
#define SMEM_DYN (SM_BUF + 2 * BUFSZ)   // 118784

// ---------------- device scratch ----------------
__device__ __align__(16) float g_c0 [BB * HH];
__device__ __align__(16) float g_c1 [BB * HH];
__device__ __align__(16) float g_enc[(size_t)BB * SS * HH];   // fp32 encoder out
__device__ __align__(16) float g_q  [BB * HH];
__device__ __align__(16) float g_ctx[BB * HH];
__device__ __align__(16) float g_cc [BB * HH];
__device__ __align__(16) float g_hd [BB * HH];
__device__ __align__(16) float g_pred[BB];
__device__ __align__(16) bf16  g_h0h[2][BB * HH];
__device__ __align__(16) bf16  g_h0l[2][BB * HH];
__device__ __align__(16) bf16  g_h1h[2][BB * HH];
__device__ __align__(16) bf16  g_h1l[2][BB * HH];
#define WR_ELEMS ((size_t)4 * 32 * 64 * 512)
__device__ __align__(16) bf16 g_wrh[WR_ELEMS];
__device__ __align__(16) bf16 g_wrl[WR_ELEMS];
__device__ unsigned g_barE[4];
__device__ unsigned g_barD[4];

// ---------------- PTX helpers ----------------
__device__ __forceinline__ uint32_t smem_u32(const void* p) {
    uint32_t a;
    asm("{ .reg .u64 t; cvta.to.shared.u64 t, %1; cvt.u32.u64 %0, t; }" : "=r"(a) : "l"(p));
    return a;
}
__device__ __forceinline__ void cpa_cg(uint32_t s, const void* g) {
    asm volatile("cp.async.cg.shared.global [%0], [%1], 16;" :: "r"(s), "l"(g));
}
__device__ __forceinline__ void cpa_commit() { asm volatile("cp.async.commit_group;"); }
template<int N>
__device__ __forceinline__ void cpa_wait() { asm volatile("cp.async.wait_group %0;" :: "n"(N)); }

__device__ __forceinline__ void ldm4(uint32_t* r, uint32_t a) {
    asm volatile("ldmatrix.sync.aligned.m8n8.x4.shared.b16 {%0,%1,%2,%3}, [%4];"
        : "=r"(r[0]), "=r"(r[1]), "=r"(r[2]), "=r"(r[3]) : "r"(a));
}
__device__ __forceinline__ void mma16816(float* d, const uint32_t* a, const uint32_t* b) {
    asm volatile("mma.sync.aligned.m16n8k16.row.col.f32.bf16.bf16.f32 "
        "{%0,%1,%2,%3}, {%4,%5,%6,%7}, {%8,%9}, {%0,%1,%2,%3};"
        : "+f"(d[0]), "+f"(d[1]), "+f"(d[2]), "+f"(d[3])
        : "r"(a[0]), "r"(a[1]), "r"(a[2]), "r"(a[3]), "r"(b[0]), "r"(b[1]));
}

__device__ __forceinline__ ull pack2(float x, float y) {
    ull r; asm("mov.b64 %0, {%1, %2};" : "=l"(r) : "f"(x), "f"(y)); return r;
}
__device__ __forceinline__ float2 unpack2(ull v) {
    float2 r; asm("mov.b64 {%0, %1}, %2;" : "=f"(r.x), "=f"(r.y) : "l"(v)); return r;
}
__device__ __forceinline__ void fma2(ull& d, ull a, ull b) {
    asm("fma.rn.f32x2 %0, %1, %2, %0;" : "+l"(d) : "l"(a), "l"(b));
}

// ---- activation math: 1 MUFU (ex2) each; reciprocal on FMA pipe (Newton x3) ----
__device__ __forceinline__ float ex2a(float x) {
    float r; asm("ex2.approx.f32 %0, %1;" : "=f"(r) : "f"(x)); return r;
}
__device__ __forceinline__ float nrrcp(float x) {
    // x in (1, ~1e44): magic-constant seed (~5% err) + 3 Newton steps -> ~1e-9 rel
    float y = __uint_as_float(0x7EF311C3u - __float_as_uint(x));
    y = y * (2.f - x * y);
    y = y * (2.f - x * y);
    y = y * (2.f - x * y);
    return y;
}
__device__ __forceinline__ float sigm(float x) {
    return nrrcp(1.f + ex2a(-1.44269504f * x));
}
__device__ __forceinline__ float ftanh2(float x) {
    return 2.f * nrrcp(1.f + ex2a(-2.88539008f * x)) - 1.f;
}

// per-group barrier: 32 CTAs, own counter
__device__ __forceinline__ void gbarg(unsigned* cnt, unsigned& target) {
    __threadfence();
    __syncthreads();
    target += GRP;
    if (threadIdx.x == 0) {
        atomicAdd(cnt, 1u);
        while (*(volatile unsigned*)cnt < target) { }
        __threadfence();
    }
    __syncthreads();
}

// ---------------- MMA LSTM step (R8 structure: K=64 chunks, 2-stage pipeline) ----------------
__device__ __forceinline__ void load_chunk(uint32_t sbase, int ch,
                                           const bf16* A_h, const bf16* A_l,
                                           const bf16* W_h, const bf16* W_l,
                                           int mBase, int tid)
{
    const int k0 = (ch & 7) * 64;
    const uint32_t sbuf = sbase + SM_BUF + (ch & 1) * BUFSZ;
#pragma unroll
    for (int i = 0; i < 4; i++) {
        int idx = tid + i * 256;
        int row = idx >> 3, cg = idx & 7;
        uint32_t so = row * 144 + cg * 16;
        size_t go = (size_t)(mBase + row) * 512 + k0 + cg * 8;
        cpa_cg(sbuf + OFF_AH + so, A_h + go);
        cpa_cg(sbuf + OFF_AL + so, A_l + go);
    }
#pragma unroll
    for (int i = 0; i < 2; i++) {
        int idx = tid + i * 256;
        int row = idx >> 3, cg = idx & 7;
        uint32_t so = row * 144 + cg * 16;
        size_t go = (size_t)row * 512 + k0 + cg * 8;
        cpa_cg(sbuf + OFF_BH + so, W_h + go);
        cpa_cg(sbuf + OFF_BL + so, W_l + go);
    }
    cpa_commit();
}

__device__ __forceinline__ void compute_chunk(uint32_t sbuf, float acc[2][4][4],
                                              int lane, int wm, int wn)
{
    const int q = lane >> 3, r = lane & 7;
    const uint32_t aOff = (uint32_t)(wm * 32 + (q & 1) * 8 + r) * 144 + ((q >> 1) * 8) * 2;
    const uint32_t bOff = (uint32_t)(wn * 32 + (q >> 1) * 8 + r) * 144 + ((q & 1) * 8) * 2;
    const uint32_t sAH = sbuf + OFF_AH, sAL = sbuf + OFF_AL;
    const uint32_t sBH = sbuf + OFF_BH, sBL = sbuf + OFF_BL;
#pragma unroll
    for (int ks = 0; ks < 4; ks++) {
        const uint32_t kb = ks * 32;
        uint32_t ah[2][4], al[2][4], bh[4][2], bl[4][2], t4[4];
        ldm4(ah[0], sAH + aOff + kb);
        ldm4(ah[1], sAH + aOff + 16 * 144 + kb);
        ldm4(al[0], sAL + aOff + kb);
        ldm4(al[1], sAL + aOff + 16 * 144 + kb);
        ldm4(t4, sBH + bOff + kb);
        bh[0][0] = t4[0]; bh[0][1] = t4[1]; bh[1][0] = t4[2]; bh[1][1] = t4[3];
        ldm4(t4, sBH + bOff + 16 * 144 + kb);
        bh[2][0] = t4[0]; bh[2][1] = t4[1]; bh[3][0] = t4[2]; bh[3][1] = t4[3];
        ldm4(t4, sBL + bOff + kb);
        bl[0][0] = t4[0]; bl[0][1] = t4[1]; bl[1][0] = t4[2]; bl[1][1] = t4[3];
        ldm4(t4, sBL + bOff + 16 * 144 + kb);
        bl[2][0] = t4[0]; bl[2][1] = t4[1]; bl[3][0] = t4[2]; bl[3][1] = t4[3];
#pragma unroll
        for (int fm = 0; fm < 2; fm++)
#pragma unroll
            for (int fn = 0; fn < 4; fn++) {
                mma16816(acc[fm][fn], ah[fm], bh[fn]);
                mma16816(acc[fm][fn], ah[fm], bl[fn]);
                mma16816(acc[fm][fn], al[fm], bh[fn]);
            }
    }
}

// MODE 0: enc L0 (x tail), MODE 1: enc L1 (fp32 enc out), MODE 2: decoder (+g_hd)
template<int MODE>
__device__ void lstm_step(char* sm, int nmat,
                          const bf16* Ah0, const bf16* Al0, const bf16* Wh0, const bf16* Wl0,
                          const bf16* Ah1, const bf16* Al1, const bf16* Wh1, const bf16* Wl1,
                          int mBase, int nt, int t,
                          const float* __restrict__ x,
                          const float* __restrict__ pred,
                          int bias_off,
                          float* __restrict__ cst,
                          bf16* __restrict__ hH, bf16* __restrict__ hL,
                          float* __restrict__ fout)
{
    const int tid = threadIdx.x;
    const int lane = tid & 31, wid = tid >> 5;
    const int wm = wid >> 1, wn = wid & 1;
    const uint32_t sbase = smem_u32(sm);
    float* xs = (float*)(sm + SM_XS);

    if (MODE == 0) {
        for (int idx = tid; idx < 1024; idx += 256) {
            int row = idx >> 3, k = idx & 7;
            if (k < INW)
                xs[idx] = __ldg(x + (size_t)(mBase + row) * (SS * INW) + t * INW + k);
        }
    }
    if (MODE == 2) {
        if (tid < 128) xs[tid] = __ldcg(pred + mBase + tid);
    }

    float acc[2][4][4];
#pragma unroll
    for (int i = 0; i < 2; i++)
#pragma unroll
        for (int j = 0; j < 4; j++)
#pragma unroll
            for (int k = 0; k < 4; k++) acc[i][j][k] = 0.f;

    const int nch = nmat * 8;
    load_chunk(sbase, 0, Ah0, Al0, Wh0, Wl0, mBase, tid);
    for (int c = 0; c < nch; c++) {
        if (c + 1 < nch) {
            const int m1 = (c + 1) >> 3;
            load_chunk(sbase, c + 1, m1 ? Ah1 : Ah0, m1 ? Al1 : Al0,
                       m1 ? Wh1 : Wh0, m1 ? Wl1 : Wl0, mBase, tid);
            cpa_wait<1>();
        } else {
            cpa_wait<0>();
        }
        __syncthreads();
        compute_chunk(sbase + SM_BUF + (c & 1) * BUFSZ, acc, lane, wm, wn);
        __syncthreads();
    }

    const float* bias = (const float*)(sm + bias_off);
    const float* xw = (const float*)(sm + SM_XW);
    const int rr = lane >> 2, cp = lane & 3, p = cp & 1;
#pragma unroll
    for (int fm = 0; fm < 2; fm++)
#pragma unroll
        for (int fn = 0; fn < 4; fn++) {
            float v0 = acc[fm][fn][0], v1 = acc[fm][fn][1];
            float v2 = acc[fm][fn][2], v3 = acc[fm][fn][3];
            float w0 = __shfl_xor_sync(0xffffffffu, v0, 1);
            float w1 = __shfl_xor_sync(0xffffffffu, v1, 1);
            float w2 = __shfl_xor_sync(0xffffffffu, v2, 1);
            float w3 = __shfl_xor_sync(0xffffffffu, v3, 1);
            const int ul = wn * 8 + fn * 2 + (cp >> 1);
            const int b = mBase + wm * 32 + fm * 16 + rr + (p ? 8 : 0);
            float gi, gf, gg, go;
            if (p == 0) { gi = v0; gf = v1; gg = w0; go = w1; }
            else        { gi = w2; gf = w3; gg = v2; go = v3; }
            const int j0 = ul * 4;
            gi += bias[j0 + 0];
            gf += bias[j0 + 1];
            gg += bias[j0 + 2];
            go += bias[j0 + 3];
            if (MODE == 0) {
                const float* xr = xs + (b - mBase) * 8;
#pragma unroll
                for (int k = 0; k < INW; k++) {
                    float xv = xr[k];
                    gi += xv * xw[(j0 + 0) * 8 + k];
                    gf += xv * xw[(j0 + 1) * 8 + k];
                    gg += xv * xw[(j0 + 2) * 8 + k];
                    go += xv * xw[(j0 + 3) * 8 + k];
                }
            }
            if (MODE == 2) {
                float pb = xs[b - mBase];
                gi += pb * xw[j0 + 0];
                gf += pb * xw[j0 + 1];
                gg += pb * xw[j0 + 2];
                go += pb * xw[j0 + 3];
            }
            const int hid = nt * 16 + ul;
            const int idx = b * 512 + hid;
            float si = sigm(gi);
            float sf = sigm(gf);
            float so = sigm(go);
            float cn = sf * cst[idx] + si * ftanh2(gg);
            float hn = so * ftanh2(cn);
            cst[idx] = cn;
            bf16 hh = __float2bfloat16(hn);
            hH[idx] = hh;
            hL[idx] = __float2bfloat16(hn - __bfloat162float(hh));
            if (MODE == 1) fout[(size_t)b * (SS * HH) + hid] = hn;
            if (MODE == 2) fout[idx] = hn;
        }
}

// ---------------- SIMT decoder pieces ----------------
__device__ void gemm32_tile(float* sm,
                            const float* __restrict__ A1, int K1,
                            const float* __restrict__ A2, int K2,
                            const float* __restrict__ W, int ldw,
                            const float* __restrict__ bias,
                            float* __restrict__ out, int act,
                            const float* __restrict__ fcW, float* __restrict__ predOut)
{
    float (*As)[36] = (float(*)[36])sm;
    float (*Bs)[68] = (float(*)[68])(sm + 16 * 36);
    const int tid = threadIdx.x;
    const int tx = tid & 15, ty = tid >> 4;
    const int mBase = ((int)blockIdx.x >> 3) * 32;
    const int nBase = ((int)blockIdx.x & 7) * 64;
    ull acc2[2][2] = {{0ull, 0ull}, {0ull, 0ull}};
    for (int part = 0; part < 2; part++) {
        const float* A = part ? A2 : A1;
        const int K = part ? K2 : K1;
        const int coff = part ? K1 : 0;
        if (A == nullptr || K == 0) continue;
        for (int k0 = 0; k0 < K; k0 += 16) {
            {   int m = tid >> 3, kc = tid & 7;
                float2 v = __ldcg((const float2*)(A + (size_t)(mBase + m) * K + k0 + kc * 2));
                As[kc * 2 + 0][m] = v.x;
                As[kc * 2 + 1][m] = v.y;
            }
            {   int rr = tid >> 2, kc = tid & 3;
                float4 v = *(const float4*)(W + (size_t)(nBase + rr) * ldw + coff + k0 + kc * 4);
                Bs[kc * 4 + 0][rr] = v.x;
                Bs[kc * 4 + 1][rr] = v.y;
                Bs[kc * 4 + 2][rr] = v.z;
                Bs[kc * 4 + 3][rr] = v.w;
            }
            __syncthreads();
#pragma unroll
            for (int k = 0; k < 16; k++) {
                ull av[2];
#pragma unroll
                for (int i = 0; i < 2; i++) { float a = As[k][ty * 2 + i]; av[i] = pack2(a, a); }
                ull bv0 = *(const ull*)&Bs[k][tx * 4];
                ull bv1 = *(const ull*)&Bs[k][tx * 4 + 2];
#pragma unroll
                for (int i = 0; i < 2; i++) { fma2(acc2[i][0], av[i], bv0); fma2(acc2[i][1], av[i], bv1); }
            }
            __syncthreads();
        }
    }
    float fcp[2] = {0.f, 0.f};
#pragma unroll
    for (int i = 0; i < 2; i++)
#pragma unroll
        for (int jp = 0; jp < 2; jp++) {
            float2 v = unpack2(acc2[i][jp]);
            int row = mBase + ty * 2 + i;
            int col = nBase + tx * 4 + jp * 2;
            float v0 = v.x + (bias ? bias[col] : 0.f);
            float v1 = v.y + (bias ? bias[col + 1] : 0.f);
            if (act) { v0 = ftanh2(v0); v1 = ftanh2(v1); }
            out[row * 512 + col] = v0;
            out[row * 512 + col + 1] = v1;
            if (fcW) fcp[i] += v0 * __ldg(fcW + col) + v1 * __ldg(fcW + col + 1);
        }
    if (fcW) {
#pragma unroll
        for (int o = 1; o < 16; o <<= 1) {
            fcp[0] += __shfl_xor_sync(0xffffffffu, fcp[0], o);
            fcp[1] += __shfl_xor_sync(0xffffffffu, fcp[1], o);
        }
        if (tx == 0) {
            atomicAdd(&predOut[mBase + ty * 2 + 0], fcp[0]);
            atomicAdd(&predOut[mBase + ty * 2 + 1], fcp[1]);
        }
    }
}

// attention (R8 proven fp32 path)
__device__ void attn_phase(float* sm, const float* __restrict__ enc,
                           const float* __restrict__ q, float* __restrict__ ctx)
{
    float* qs = sm; float* cs = sm + 512; float* ms = sm + 1024; float* ds = sm + 1032;
    const int tid = threadIdx.x, warp = tid >> 5, lane = tid & 31;
    for (int bi = 0; bi < 4; bi++) {
        const int b = (int)blockIdx.x * 4 + bi;
        qs[tid] = __ldcg(&q[b * 512 + tid]);
        qs[tid + 256] = __ldcg(&q[b * 512 + tid + 256]);
        cs[tid] = 0.f; cs[tid + 256] = 0.f;
        __syncthreads();
        float m = -1e30f, d = 0.f;
        float cacc[16];
#pragma unroll
        for (int k = 0; k < 16; k++) cacc[k] = 0.f;
        const float* base = enc + (size_t)b * SS * HH;
        for (int s0 = warp * 2; s0 < SS; s0 += 16) {
            const float* r0 = base + (size_t)s0 * 512;
            const float* r1 = r0 + 512;
            float4 v0[4], v1[4];
            float p0 = 0.f, p1 = 0.f;
#pragma unroll
            for (int ch = 0; ch < 4; ch++) {
                v0[ch] = __ldcs((const float4*)(r0 + ch * 128 + lane * 4));
                v1[ch] = __ldcs((const float4*)(r1 + ch * 128 + lane * 4));
            }
#pragma unroll
            for (int ch = 0; ch < 4; ch++) {
                float4 qv = *(const float4*)(qs + ch * 128 + lane * 4);
                p0 += v0[ch].x * qv.x + v0[ch].y * qv.y + v0[ch].z * qv.z + v0[ch].w * qv.w;
                p1 += v1[ch].x * qv.x + v1[ch].y * qv.y + v1[ch].z * qv.z + v1[ch].w * qv.w;
            }
#pragma unroll
            for (int o = 16; o; o >>= 1) {
                p0 += __shfl_xor_sync(0xffffffffu, p0, o);
                p1 += __shfl_xor_sync(0xffffffffu, p1, o);
            }
            {   float mn = fmaxf(m, p0);
                float sc = __expf(m - mn), w = __expf(p0 - mn);
                d = d * sc + w;
#pragma unroll
                for (int ch = 0; ch < 4; ch++) {
                    cacc[ch*4+0] = cacc[ch*4+0]*sc + w*v0[ch].x;
                    cacc[ch*4+1] = cacc[ch*4+1]*sc + w*v0[ch].y;
                    cacc[ch*4+2] = cacc[ch*4+2]*sc + w*v0[ch].z;
                    cacc[ch*4+3] = cacc[ch*4+3]*sc + w*v0[ch].w;
                }
                m = mn;
            }
            {   float mn = fmaxf(m, p1);
                float sc = __expf(m - mn), w = __expf(p1 - mn);
                d = d * sc + w;
#pragma unroll
                for (int ch = 0; ch < 4; ch++) {
                    cacc[ch*4+0] = cacc[ch*4+0]*sc + w*v1[ch].x;
                    cacc[ch*4+1] = cacc[ch*4+1]*sc + w*v1[ch].y;
                    cacc[ch*4+2] = cacc[ch*4+2]*sc + w*v1[ch].z;
                    cacc[ch*4+3] = cacc[ch*4+3]*sc + w*v1[ch].w;
                }
                m = mn;
            }
        }
        if (lane == 0) { ms[warp] = m; ds[warp] = d; }
        __syncthreads();
        float M = -1e30f;
#pragma unroll
        for (int w8 = 0; w8 < 8; w8++) M = fmaxf(M, ms[w8]);
        float D = 0.f;
#pragma unroll
        for (int w8 = 0; w8 < 8; w8++) D += ds[w8] * __expf(ms[w8] - M);
        float f = __expf(m - M);
#pragma unroll
        for (int ch = 0; ch < 4; ch++) {
            atomicAdd(&cs[ch*128 + lane*4 + 0], cacc[ch*4+0] * f);
            atomicAdd(&cs[ch*128 + lane*4 + 1], cacc[ch*4+1] * f);
            atomicAdd(&cs[ch*128 + lane*4 + 2], cacc[ch*4+2] * f);
            atomicAdd(&cs[ch*128 + lane*4 + 3], cacc[ch*4+3] * f);
        }
        __syncthreads();
        float invD = 1.f / D;
        ctx[b * 512 + tid] = cs[tid] * invD;
        ctx[b * 512 + tid + 256] = cs[tid + 256] * invD;
        __syncthreads();
    }
}

// ---------------- prep kernels ----------------
__global__ void prep_weights(const float* __restrict__ Whh0, const float* __restrict__ Whh1,
                             const float* __restrict__ Wih1, const float* __restrict__ dWhh)
{
    const float* mats[4] = {Whh0, Whh1, Wih1, dWhh};
    for (size_t i = (size_t)blockIdx.x * 256 + threadIdx.x; i < WR_ELEMS;
         i += (size_t)gridDim.x * 256) {
        int k  = (int)(i & 511);
        int j  = (int)((i >> 9) & 63);
        int nt = (int)((i >> 15) & 31);
        int m  = (int)(i >> 20);
        int row = (j & 3) * 512 + nt * 16 + (j >> 2);
        float v = __ldg(mats[m] + (size_t)row * 512 + k);
        bf16 h = __float2bfloat16(v);
        g_wrh[i] = h;
        g_wrl[i] = __float2bfloat16(v - __bfloat162float(h));
    }
}

__global__ void init_pred_kernel(const float* __restrict__ x, float* __restrict__ pred)
{
    int b = blockIdx.x * 256 + threadIdx.x;
    if (b < BB) pred[b] = x[(size_t)b * (SS * INW) + (SS - 1) * INW + (INW - 1)];
}

// ---------------- persistent encoder: per-group barriers (R8 structure) ----------------
__global__ __launch_bounds__(256, 1)
void enc_persist(const float* __restrict__ x, const float* __restrict__ Wih0,
                 const float* __restrict__ b0, const float* __restrict__ b1,
                 unsigned* barArr)
{
    extern __shared__ __align__(16) char sm[];
    const int tid = threadIdx.x;
    const int grp = (int)blockIdx.x >> 5;
    const int mBase = grp * 128;
    const int nt = (int)blockIdx.x & 31;
    unsigned* bar = barArr + grp;

    float* bias0 = (float*)(sm + SM_BIAS0);
    float* bias1 = (float*)(sm + SM_BIAS1);
    float* xw    = (float*)(sm + SM_XW);
    if (tid < 64) {
        int j = tid, row = (j & 3) * 512 + nt * 16 + (j >> 2);
        bias0[j] = __ldg(b0 + row);
        bias1[j] = __ldg(b1 + row);
        for (int k = 0; k < INW; k++) xw[j * 8 + k] = __ldg(Wih0 + (size_t)row * INW + k);
    }
    __syncthreads();

    const size_t tsz = (size_t)64 * 512;
    const bf16* w0h = g_wrh + (size_t)(0 * 32 + nt) * tsz;
    const bf16* w0l = g_wrl + (size_t)(0 * 32 + nt) * tsz;
    const bf16* w1h = g_wrh + (size_t)(1 * 32 + nt) * tsz;
    const bf16* w1l = g_wrl + (size_t)(1 * 32 + nt) * tsz;
    const bf16* w2h = g_wrh + (size_t)(2 * 32 + nt) * tsz;
    const bf16* w2l = g_wrl + (size_t)(2 * 32 + nt) * tsz;

    unsigned target = 0;
    for (int t = 0; t < SS; t++) {
        const int rp = t & 1, wp = 1 - rp;
        lstm_step<0>(sm, 1,
                     g_h0h[rp], g_h0l[rp], w0h, w0l,
                     nullptr, nullptr, nullptr, nullptr,
                     mBase, nt, t, x, nullptr, SM_BIAS0,
                     g_c0, g_h0h[wp], g_h0l[wp], nullptr);
        gbarg(bar, target);
        lstm_step<1>(sm, 2,
                     g_h1h[rp], g_h1l[rp], w1h, w1l,
                     g_h0h[wp], g_h0l[wp], w2h, w2l,
                     mBase, nt, t, nullptr, nullptr, SM_BIAS1,
                     g_c1, g_h1h[wp], g_h1l[wp], g_enc + (size_t)t * HH);
        gbarg(bar, target);
    }
}

// ---------------- persistent decoder: per-group barriers, 4 phases/step ----------------
__global__ __launch_bounds__(256, 1)
void dec_persist(const float* __restrict__ dWih, const float* __restrict__ db,
                 const float* __restrict__ attW, const float* __restrict__ catW,
                 const float* __restrict__ catb, const float* __restrict__ fcW,
                 const float* __restrict__ fcb, float* __restrict__ out, unsigned* barArr)
{
    extern __shared__ __align__(16) char sm[];
    const int tid = threadIdx.x;
    const int grp = (int)blockIdx.x >> 5;
    const int mBase = grp * 128;
    const int nt = (int)blockIdx.x & 31;
    unsigned* bar = barArr + grp;

    float* bias0 = (float*)(sm + SM_BIAS0);
    float* xw    = (float*)(sm + SM_XW);
    if (tid < 64) {
        int j = tid, row = (j & 3) * 512 + nt * 16 + (j >> 2);
        bias0[j] = __ldg(db + row);
        xw[j] = __ldg(dWih + row);
    }
    __syncthreads();
    const float fcb0 = __ldg(fcb);

    const size_t tsz = (size_t)64 * 512;
    const bf16* dwh = g_wrh + (size_t)(3 * 32 + nt) * tsz;
    const bf16* dwl = g_wrl + (size_t)(3 * 32 + nt) * tsz;

    unsigned target = 0;
    for (int t = 0; t < TT; t++) {
        const int rp = t & 1, wp = 1 - rp;
        if (nt == 0 && t > 0 && tid < 128)
            out[(size_t)(mBase + tid) * TT + (t - 1)] = __ldcg(&g_pred[mBase + tid]);
        lstm_step<2>(sm, 1,
                     g_h1h[rp], g_h1l[rp], dwh, dwl,
                     nullptr, nullptr, nullptr, nullptr,
                     mBase, nt, t, nullptr, g_pred, SM_BIAS0,
                     g_c1, g_h1h[wp], g_h1l[wp], g_hd);
        gbarg(bar, target);
        if (nt == 0 && tid < 128) g_pred[mBase + tid] = fcb0;
        gemm32_tile((float*)(sm + SM_BUF), g_hd, 512, nullptr, 0, attW, 512,
                    nullptr, g_q, 0, nullptr, nullptr);
        gbarg(bar, target);
        attn_phase((float*)(sm + SM_BUF), g_enc, g_q, g_ctx);
        gbarg(bar, target);
        gemm32_tile((float*)(sm + SM_BUF), g_hd, 512, g_ctx, 512, catW, 1024,
                    catb, g_cc, 1, fcW, g_pred);
        gbarg(bar, target);
    }
    if (nt == 0 && tid < 128)
        out[(size_t)(mBase + tid) * TT + (TT - 1)] = __ldcg(&g_pred[mBase + tid]);
}

// ---------------- host ----------------
extern "C" void kernel_launch(void* const* d_in, const int* in_sizes, int n_in,
                              void* d_out, int out_size)
{
    const float* x    = (const float*)d_in[0];
    const float* Wih0 = (const float*)d_in[1];
    const float* Whh0 = (const float*)d_in[2];
    const float* b0   = (const float*)d_in[3];
    const float* Wih1 = (const float*)d_in[4];
    const float* Whh1 = (const float*)d_in[5];
    const float* b1   = (const float*)d_in[6];
    const float* dWih = (const float*)d_in[7];
    const float* dWhh = (const float*)d_in[8];
    const float* db   = (const float*)d_in[9];
    const float* attW = (const float*)d_in[10];
    const float* catW = (const float*)d_in[11];
    const float* catb = (const float*)d_in[12];
    const float* fcW  = (const float*)d_in[13];
    const float* fcb  = (const float*)d_in[14];
    float* out = (float*)d_out;

    static int once = 0;
    if (!once) {
        cudaFuncSetAttribute(enc_persist, cudaFuncAttributeMaxDynamicSharedMemorySize, SMEM_DYN);
        cudaFuncSetAttribute(dec_persist, cudaFuncAttributeMaxDynamicSharedMemorySize, SMEM_DYN);
        once = 1;
    }

    float *c0p, *c1p, *predp;
    bf16 *h0hp, *h0lp, *h1hp, *h1lp;
    unsigned *barE, *barD;
    cudaGetSymbolAddress((void**)&c0p,  g_c0);
    cudaGetSymbolAddress((void**)&c1p,  g_c1);
    cudaGetSymbolAddress((void**)&predp,g_pred);
    cudaGetSymbolAddress((void**)&h0hp, g_h0h);
    cudaGetSymbolAddress((void**)&h0lp, g_h0l);
    cudaGetSymbolAddress((void**)&h1hp, g_h1h);
    cudaGetSymbolAddress((void**)&h1lp, g_h1l);
    cudaGetSymbolAddress((void**)&barE, g_barE);
    cudaGetSymbolAddress((void**)&barD, g_barD);

    const size_t sf = (size_t)BB * HH * sizeof(float);
    const size_t sh2 = (size_t)2 * BB * HH * sizeof(bf16);
    cudaMemsetAsync(c0p, 0, sf);
    cudaMemsetAsync(c1p, 0, sf);
    cudaMemsetAsync(h0hp, 0, sh2);
    cudaMemsetAsync(h0lp, 0, sh2);
    cudaMemsetAsync(h1hp, 0, sh2);
    cudaMemsetAsync(h1lp, 0, sh2);
    cudaMemsetAsync(barE, 0, 4 * sizeof(unsigned));
    cudaMemsetAsync(barD, 0, 4 * sizeof(unsigned));

    prep_weights<<<1024, 256>>>(Whh0, Whh1, Wih1, dWhh);
    init_pred_kernel<<<2, 256>>>(x, predp);

    enc_persist<<<NCTA, 256, SMEM_DYN>>>(x, Wih0, b0, b1, barE);
    dec_persist<<<NCTA, 256, SMEM_DYN>>>(dWih, db, attW, catW, catb, fcW, fcb, out, barD);
}

// round 12
// speedup vs baseline: 1.2214x; 1.2214x over previous
#include <cuda_runtime.h>
#include <cuda_bf16.h>
#include <cuda_fp16.h>
#include <cstdint>

#define BB 512
#define SS 336
#define INW 7
#define HH 512
#define TT 96
#define NCTA 128
#define GRP 32    // CTAs per independent group

typedef unsigned long long ull;

// ---------------- smem layout (bytes) ----------------
#define SM_BIAS0 0
#define SM_BIAS1 256
#define SM_XW    512
#define SM_XS    2560
#define SM_BUF   8192
#define OFF_AH   0            // 128 rows * 144B
#define OFF_AL   18432
#define OFF_B    36864        // 64 rows * 144B
#define BUFSZ    46080
#define SMEM_DYN (SM_BUF + 2 * BUFSZ)   // 100352

// ---------------- device scratch ----------------
__device__ __align__(16) float g_c0 [BB * HH];
__device__ __align__(16) float g_c1 [BB * HH];
__device__ __align__(16) float g_enc[(size_t)BB * SS * HH];   // fp32 encoder out
__device__ __align__(16) float g_q  [BB * HH];
__device__ __align__(16) float g_ctx[BB * HH];
__device__ __align__(16) float g_cc [BB * HH];
__device__ __align__(16) float g_hd [BB * HH];
__device__ __align__(16) float g_pred[BB];
__device__ __align__(16) __half g_h0h[2][BB * HH];
__device__ __align__(16) __half g_h0l[2][BB * HH];
__device__ __align__(16) __half g_h1h[2][BB * HH];
__device__ __align__(16) __half g_h1l[2][BB * HH];
// reordered weights (fp16 single): [mat(4)][nt(32)][j(64)][k(512)], j=u*4+g
#define WR_ELEMS ((size_t)4 * 32 * 64 * 512)
__device__ __align__(16) __half g_wf[WR_ELEMS];
__device__ unsigned g_barE[4];
__device__ unsigned g_barD[4];

// ---------------- PTX helpers ----------------
__device__ __forceinline__ uint32_t smem_u32(const void* p) {
    uint32_t a;
    asm("{ .reg .u64 t; cvta.to.shared.u64 t, %1; cvt.u32.u64 %0, t; }" : "=r"(a) : "l"(p));
    return a;
}
__device__ __forceinline__ void cpa_cg(uint32_t s, const void* g) {
    asm volatile("cp.async.cg.shared.global [%0], [%1], 16;" :: "r"(s), "l"(g));
}
__device__ __forceinline__ void cpa_commit() { asm volatile("cp.async.commit_group;"); }
template<int N>
__device__ __forceinline__ void cpa_wait() { asm volatile("cp.async.wait_group %0;" :: "n"(N)); }

__device__ __forceinline__ void ldm4(uint32_t* r, uint32_t a) {
    asm volatile("ldmatrix.sync.aligned.m8n8.x4.shared.b16 {%0,%1,%2,%3}, [%4];"
        : "=r"(r[0]), "=r"(r[1]), "=r"(r[2]), "=r"(r[3]) : "r"(a));
}
__device__ __forceinline__ void mma16816h(float* d, const uint32_t* a, const uint32_t* b) {
    asm volatile("mma.sync.aligned.m16n8k16.row.col.f32.f16.f16.f32 "
        "{%0,%1,%2,%3}, {%4,%5,%6,%7}, {%8,%9}, {%0,%1,%2,%3};"
        : "+f"(d[0]), "+f"(d[1]), "+f"(d[2]), "+f"(d[3])
        : "r"(a[0]), "r"(a[1]), "r"(a[2]), "r"(a[3]), "r"(b[0]), "r"(b[1]));
}

__device__ __forceinline__ ull pack2(float x, float y) {
    ull r; asm("mov.b64 %0, {%1, %2};" : "=l"(r) : "f"(x), "f"(y)); return r;
}
__device__ __forceinline__ float2 unpack2(ull v) {
    float2 r; asm("mov.b64 {%0, %1}, %2;" : "=f"(r.x), "=f"(r.y) : "l"(v)); return r;
}
__device__ __forceinline__ void fma2(ull& d, ull a, ull b) {
    asm("fma.rn.f32x2 %0, %1, %2, %0;" : "+l"(d) : "l"(a), "l"(b));
}

__device__ __forceinline__ float ftanh(float x) {
    return 1.f - 2.f / (__expf(2.f * x) + 1.f);
}

// per-group barrier: 32 CTAs, own counter
__device__ __forceinline__ void gbarg(unsigned* cnt, unsigned& target) {
    __threadfence();
    __syncthreads();
    target += GRP;
    if (threadIdx.x == 0) {
        atomicAdd(cnt, 1u);
        while (*(volatile unsigned*)cnt < target) { }
        __threadfence();
    }
    __syncthreads();
}

// ---------------- MMA LSTM step: K=64 chunks, 2-stage pipeline, 2-term fp16 ----------------
__device__ __forceinline__ void load_chunk(uint32_t sbase, int ch,
                                           const __half* A_h, const __half* A_l,
                                           const __half* W_f,
                                           int mBase, int tid)
{
    const int k0 = (ch & 7) * 64;
    const uint32_t sbuf = sbase + SM_BUF + (ch & 1) * BUFSZ;
#pragma unroll
    for (int i = 0; i < 4; i++) {
        int idx = tid + i * 256;
        int row = idx >> 3, cg = idx & 7;
        uint32_t so = row * 144 + cg * 16;
        size_t go = (size_t)(mBase + row) * 512 + k0 + cg * 8;
        cpa_cg(sbuf + OFF_AH + so, A_h + go);
        cpa_cg(sbuf + OFF_AL + so, A_l + go);
    }
#pragma unroll
    for (int i = 0; i < 2; i++) {
        int idx = tid + i * 256;
        int row = idx >> 3, cg = idx & 7;
        uint32_t so = row * 144 + cg * 16;
        size_t go = (size_t)row * 512 + k0 + cg * 8;
        cpa_cg(sbuf + OFF_B + so, W_f + go);
    }
    cpa_commit();
}

__device__ __forceinline__ void compute_chunk(uint32_t sbuf, float acc[2][4][4],
                                              int lane, int wm, int wn)
{
    const int q = lane >> 3, r = lane & 7;
    const uint32_t aOff = (uint32_t)(wm * 32 + (q & 1) * 8 + r) * 144 + ((q >> 1) * 8) * 2;
    const uint32_t bOff = (uint32_t)(wn * 32 + (q >> 1) * 8 + r) * 144 + ((q & 1) * 8) * 2;
    const uint32_t sAH = sbuf + OFF_AH, sAL = sbuf + OFF_AL;
    const uint32_t sB  = sbuf + OFF_B;
#pragma unroll
    for (int ks = 0; ks < 4; ks++) {
        const uint32_t kb = ks * 32;
        uint32_t ah[2][4], al[2][4], bf[4][2], t4[4];
        ldm4(ah[0], sAH + aOff + kb);
        ldm4(ah[1], sAH + aOff + 16 * 144 + kb);
        ldm4(al[0], sAL + aOff + kb);
        ldm4(al[1], sAL + aOff + 16 * 144 + kb);
        ldm4(t4, sB + bOff + kb);
        bf[0][0] = t4[0]; bf[0][1] = t4[1]; bf[1][0] = t4[2]; bf[1][1] = t4[3];
        ldm4(t4, sB + bOff + 16 * 144 + kb);
        bf[2][0] = t4[0]; bf[2][1] = t4[1]; bf[3][0] = t4[2]; bf[3][1] = t4[3];
#pragma unroll
        for (int fm = 0; fm < 2; fm++)
#pragma unroll
            for (int fn = 0; fn < 4; fn++) {
                mma16816h(acc[fm][fn], ah[fm], bf[fn]);
                mma16816h(acc[fm][fn], al[fm], bf[fn]);
            }
    }
}

// MODE 0: enc L0 (x tail), MODE 1: enc L1 (fp32 enc out), MODE 2: decoder (+g_hd)
template<int MODE>
__device__ void lstm_step(char* sm, int nmat,
                          const __half* Ah0, const __half* Al0, const __half* W0,
                          const __half* Ah1, const __half* Al1, const __half* W1,
                          int mBase, int nt, int t,
                          const float* __restrict__ x,
                          const float* __restrict__ pred,
                          int bias_off,
                          float* __restrict__ cst,
                          __half* __restrict__ hH, __half* __restrict__ hL,
                          float* __restrict__ fout)
{
    const int tid = threadIdx.x;
    const int lane = tid & 31, wid = tid >> 5;
    const int wm = wid >> 1, wn = wid & 1;
    const uint32_t sbase = smem_u32(sm);
    float* xs = (float*)(sm + SM_XS);

    if (MODE == 0) {
        for (int idx = tid; idx < 1024; idx += 256) {
            int row = idx >> 3, k = idx & 7;
            if (k < INW)
                xs[idx] = __ldg(x + (size_t)(mBase + row) * (SS * INW) + t * INW + k);
        }
    }
    if (MODE == 2) {
        if (tid < 128) xs[tid] = __ldcg(pred + mBase + tid);
    }

    float acc[2][4][4];
#pragma unroll
    for (int i = 0; i < 2; i++)
#pragma unroll
        for (int j = 0; j < 4; j++)
#pragma unroll
            for (int k = 0; k < 4; k++) acc[i][j][k] = 0.f;

    const int nch = nmat * 8;
    load_chunk(sbase, 0, Ah0, Al0, W0, mBase, tid);
    for (int c = 0; c < nch; c++) {
        if (c + 1 < nch) {
            const int m1 = (c + 1) >> 3;
            load_chunk(sbase, c + 1, m1 ? Ah1 : Ah0, m1 ? Al1 : Al0,
                       m1 ? W1 : W0, mBase, tid);
            cpa_wait<1>();
        } else {
            cpa_wait<0>();
        }
        __syncthreads();
        compute_chunk(sbase + SM_BUF + (c & 1) * BUFSZ, acc, lane, wm, wn);
        __syncthreads();
    }

    const float* bias = (const float*)(sm + bias_off);
    const float* xw = (const float*)(sm + SM_XW);
    const int rr = lane >> 2, cp = lane & 3, p = cp & 1;
#pragma unroll
    for (int fm = 0; fm < 2; fm++)
#pragma unroll
        for (int fn = 0; fn < 4; fn++) {
            float v0 = acc[fm][fn][0], v1 = acc[fm][fn][1];
            float v2 = acc[fm][fn][2], v3 = acc[fm][fn][3];
            float w0 = __shfl_xor_sync(0xffffffffu, v0, 1);
            float w1 = __shfl_xor_sync(0xffffffffu, v1, 1);
            float w2 = __shfl_xor_sync(0xffffffffu, v2, 1);
            float w3 = __shfl_xor_sync(0xffffffffu, v3, 1);
            const int ul = wn * 8 + fn * 2 + (cp >> 1);
            const int b = mBase + wm * 32 + fm * 16 + rr + (p ? 8 : 0);
            float gi, gf, gg, go;
            if (p == 0) { gi = v0; gf = v1; gg = w0; go = w1; }
            else        { gi = w2; gf = w3; gg = v2; go = v3; }
            const int j0 = ul * 4;
            gi += bias[j0 + 0];
            gf += bias[j0 + 1];
            gg += bias[j0 + 2];
            go += bias[j0 + 3];
            if (MODE == 0) {
                const float* xr = xs + (b - mBase) * 8;
#pragma unroll
                for (int k = 0; k < INW; k++) {
                    float xv = xr[k];
                    gi += xv * xw[(j0 + 0) * 8 + k];
                    gf += xv * xw[(j0 + 1) * 8 + k];
                    gg += xv * xw[(j0 + 2) * 8 + k];
                    go += xv * xw[(j0 + 3) * 8 + k];
                }
            }
            if (MODE == 2) {
                float pb = xs[b - mBase];
                gi += pb * xw[j0 + 0];
                gf += pb * xw[j0 + 1];
                gg += pb * xw[j0 + 2];
                go += pb * xw[j0 + 3];
            }
            const int hid = nt * 16 + ul;
            const int idx = b * 512 + hid;
            float si = 1.f / (1.f + __expf(-gi));
            float sf = 1.f / (1.f + __expf(-gf));
            float so = 1.f / (1.f + __expf(-go));
            float cn = sf * cst[idx] + si * ftanh(gg);
            float hn = so * ftanh(cn);
            cst[idx] = cn;
            __half hh = __float2half(hn);
            hH[idx] = hh;
            hL[idx] = __float2half(hn - __half2float(hh));
            if (MODE == 1) fout[(size_t)b * (SS * HH) + hid] = hn;
            if (MODE == 2) fout[idx] = hn;
        }
}

// ---------------- SIMT decoder pieces (R8 verbatim) ----------------
__device__ void gemm32_tile(float* sm,
                            const float* __restrict__ A1, int K1,
                            const float* __restrict__ A2, int K2,
                            const float* __restrict__ W, int ldw,
                            const float* __restrict__ bias,
                            float* __restrict__ out, int act,
                            const float* __restrict__ fcW, float* __restrict__ predOut)
{
    float (*As)[36] = (float(*)[36])sm;
    float (*Bs)[68] = (float(*)[68])(sm + 16 * 36);
    const int tid = threadIdx.x;
    const int tx = tid & 15, ty = tid >> 4;
    const int mBase = ((int)blockIdx.x >> 3) * 32;
    const int nBase = ((int)blockIdx.x & 7) * 64;
    ull acc2[2][2] = {{0ull, 0ull}, {0ull, 0ull}};
    for (int part = 0; part < 2; part++) {
        const float* A = part ? A2 : A1;
        const int K = part ? K2 : K1;
        const int coff = part ? K1 : 0;
        if (A == nullptr || K == 0) continue;
        for (int k0 = 0; k0 < K; k0 += 16) {
            {   int m = tid >> 3, kc = tid & 7;
                float2 v = __ldcg((const float2*)(A + (size_t)(mBase + m) * K + k0 + kc * 2));
                As[kc * 2 + 0][m] = v.x;
                As[kc * 2 + 1][m] = v.y;
            }
            {   int rr = tid >> 2, kc = tid & 3;
                float4 v = *(const float4*)(W + (size_t)(nBase + rr) * ldw + coff + k0 + kc * 4);
                Bs[kc * 4 + 0][rr] = v.x;
                Bs[kc * 4 + 1][rr] = v.y;
                Bs[kc * 4 + 2][rr] = v.z;
                Bs[kc * 4 + 3][rr] = v.w;
            }
            __syncthreads();
#pragma unroll
            for (int k = 0; k < 16; k++) {
                ull av[2];
#pragma unroll
                for (int i = 0; i < 2; i++) { float a = As[k][ty * 2 + i]; av[i] = pack2(a, a); }
                ull bv0 = *(const ull*)&Bs[k][tx * 4];
                ull bv1 = *(const ull*)&Bs[k][tx * 4 + 2];
#pragma unroll
                for (int i = 0; i < 2; i++) { fma2(acc2[i][0], av[i], bv0); fma2(acc2[i][1], av[i], bv1); }
            }
            __syncthreads();
        }
    }
    float fcp[2] = {0.f, 0.f};
#pragma unroll
    for (int i = 0; i < 2; i++)
#pragma unroll
        for (int jp = 0; jp < 2; jp++) {
            float2 v = unpack2(acc2[i][jp]);
            int row = mBase + ty * 2 + i;
            int col = nBase + tx * 4 + jp * 2;
            float v0 = v.x + (bias ? bias[col] : 0.f);
            float v1 = v.y + (bias ? bias[col + 1] : 0.f);
            if (act) { v0 = ftanh(v0); v1 = ftanh(v1); }
            out[row * 512 + col] = v0;
            out[row * 512 + col + 1] = v1;
            if (fcW) fcp[i] += v0 * __ldg(fcW + col) + v1 * __ldg(fcW + col + 1);
        }
    if (fcW) {
#pragma unroll
        for (int o = 1; o < 16; o <<= 1) {
            fcp[0] += __shfl_xor_sync(0xffffffffu, fcp[0], o);
            fcp[1] += __shfl_xor_sync(0xffffffffu, fcp[1], o);
        }
        if (tx == 0) {
            atomicAdd(&predOut[mBase + ty * 2 + 0], fcp[0]);
            atomicAdd(&predOut[mBase + ty * 2 + 1], fcp[1]);
        }
    }
}

// attention (R8 proven fp32 path)
__device__ void attn_phase(float* sm, const float* __restrict__ enc,
                           const float* __restrict__ q, float* __restrict__ ctx)
{
    float* qs = sm; float* cs = sm + 512; float* ms = sm + 1024; float* ds = sm + 1032;
    const int tid = threadIdx.x, warp = tid >> 5, lane = tid & 31;
    for (int bi = 0; bi < 4; bi++) {
        const int b = (int)blockIdx.x * 4 + bi;
        qs[tid] = __ldcg(&q[b * 512 + tid]);
        qs[tid + 256] = __ldcg(&q[b * 512 + tid + 256]);
        cs[tid] = 0.f; cs[tid + 256] = 0.f;
        __syncthreads();
        float m = -1e30f, d = 0.f;
        float cacc[16];
#pragma unroll
        for (int k = 0; k < 16; k++) cacc[k] = 0.f;
        const float* base = enc + (size_t)b * SS * HH;
        for (int s0 = warp * 2; s0 < SS; s0 += 16) {
            const float* r0 = base + (size_t)s0 * 512;
            const float* r1 = r0 + 512;
            float4 v0[4], v1[4];
            float p0 = 0.f, p1 = 0.f;
#pragma unroll
            for (int ch = 0; ch < 4; ch++) {
                v0[ch] = __ldcs((const float4*)(r0 + ch * 128 + lane * 4));
                v1[ch] = __ldcs((const float4*)(r1 + ch * 128 + lane * 4));
            }
#pragma unroll
            for (int ch = 0; ch < 4; ch++) {
                float4 qv = *(const float4*)(qs + ch * 128 + lane * 4);
                p0 += v0[ch].x * qv.x + v0[ch].y * qv.y + v0[ch].z * qv.z + v0[ch].w * qv.w;
                p1 += v1[ch].x * qv.x + v1[ch].y * qv.y + v1[ch].z * qv.z + v1[ch].w * qv.w;
            }
#pragma unroll
            for (int o = 16; o; o >>= 1) {
                p0 += __shfl_xor_sync(0xffffffffu, p0, o);
                p1 += __shfl_xor_sync(0xffffffffu, p1, o);
            }
            {   float mn = fmaxf(m, p0);
                float sc = __expf(m - mn), w = __expf(p0 - mn);
                d = d * sc + w;
#pragma unroll
                for (int ch = 0; ch < 4; ch++) {
                    cacc[ch*4+0] = cacc[ch*4+0]*sc + w*v0[ch].x;
                    cacc[ch*4+1] = cacc[ch*4+1]*sc + w*v0[ch].y;
                    cacc[ch*4+2] = cacc[ch*4+2]*sc + w*v0[ch].z;
                    cacc[ch*4+3] = cacc[ch*4+3]*sc + w*v0[ch].w;
                }
                m = mn;
            }
            {   float mn = fmaxf(m, p1);
                float sc = __expf(m - mn), w = __expf(p1 - mn);
                d = d * sc + w;
#pragma unroll
                for (int ch = 0; ch < 4; ch++) {
                    cacc[ch*4+0] = cacc[ch*4+0]*sc + w*v1[ch].x;
                    cacc[ch*4+1] = cacc[ch*4+1]*sc + w*v1[ch].y;
                    cacc[ch*4+2] = cacc[ch*4+2]*sc + w*v1[ch].z;
                    cacc[ch*4+3] = cacc[ch*4+3]*sc + w*v1[ch].w;
                }
                m = mn;
            }
        }
        if (lane == 0) { ms[warp] = m; ds[warp] = d; }
        __syncthreads();
        float M = -1e30f;
#pragma unroll
        for (int w8 = 0; w8 < 8; w8++) M = fmaxf(M, ms[w8]);
        float D = 0.f;
#pragma unroll
        for (int w8 = 0; w8 < 8; w8++) D += ds[w8] * __expf(ms[w8] - M);
        float f = __expf(m - M);
#pragma unroll
        for (int ch = 0; ch < 4; ch++) {
            atomicAdd(&cs[ch*128 + lane*4 + 0], cacc[ch*4+0] * f);
            atomicAdd(&cs[ch*128 + lane*4 + 1], cacc[ch*4+1] * f);
            atomicAdd(&cs[ch*128 + lane*4 + 2], cacc[ch*4+2] * f);
            atomicAdd(&cs[ch*128 + lane*4 + 3], cacc[ch*4+3] * f);
        }
        __syncthreads();
        float invD = 1.f / D;
        ctx[b * 512 + tid] = cs[tid] * invD;
        ctx[b * 512 + tid + 256] = cs[tid + 256] * invD;
        __syncthreads();
    }
}

// ---------------- prep kernels ----------------
__global__ void prep_weights(const float* __restrict__ Whh0, const float* __restrict__ Whh1,
                             const float* __restrict__ Wih1, const float* __restrict__ dWhh)
{
    const float* mats[4] = {Whh0, Whh1, Wih1, dWhh};
    for (size_t i = (size_t)blockIdx.x * 256 + threadIdx.x; i < WR_ELEMS;
         i += (size_t)gridDim.x * 256) {
        int k  = (int)(i & 511);
        int j  = (int)((i >> 9) & 63);
        int nt = (int)((i >> 15) & 31);
        int m  = (int)(i >> 20);
        int row = (j & 3) * 512 + nt * 16 + (j >> 2);
        g_wf[i] = __float2half(__ldg(mats[m] + (size_t)row * 512 + k));
    }
}

__global__ void init_pred_kernel(const float* __restrict__ x, float* __restrict__ pred)
{
    int b = blockIdx.x * 256 + threadIdx.x;
    if (b < BB) pred[b] = x[(size_t)b * (SS * INW) + (SS - 1) * INW + (INW - 1)];
}

// ---------------- persistent encoder: per-group barriers (R8 structure) ----------------
__global__ __launch_bounds__(256, 1)
void enc_persist(const float* __restrict__ x, const float* __restrict__ Wih0,
                 const float* __restrict__ b0, const float* __restrict__ b1,
                 unsigned* barArr)
{
    extern __shared__ __align__(16) char sm[];
    const int tid = threadIdx.x;
    const int grp = (int)blockIdx.x >> 5;
    const int mBase = grp * 128;
    const int nt = (int)blockIdx.x & 31;
    unsigned* bar = barArr + grp;

    float* bias0 = (float*)(sm + SM_BIAS0);
    float* bias1 = (float*)(sm + SM_BIAS1);
    float* xw    = (float*)(sm + SM_XW);
    if (tid < 64) {
        int j = tid, row = (j & 3) * 512 + nt * 16 + (j >> 2);
        bias0[j] = __ldg(b0 + row);
        bias1[j] = __ldg(b1 + row);
        for (int k = 0; k < INW; k++) xw[j * 8 + k] = __ldg(Wih0 + (size_t)row * INW + k);
    }
    __syncthreads();

    const size_t tsz = (size_t)64 * 512;
    const __half* w0 = g_wf + (size_t)(0 * 32 + nt) * tsz;
    const __half* w1 = g_wf + (size_t)(1 * 32 + nt) * tsz;
    const __half* w2 = g_wf + (size_t)(2 * 32 + nt) * tsz;

    unsigned target = 0;
    for (int t = 0; t < SS; t++) {
        const int rp = t & 1, wp = 1 - rp;
        lstm_step<0>(sm, 1,
                     g_h0h[rp], g_h0l[rp], w0,
                     nullptr, nullptr, nullptr,
                     mBase, nt, t, x, nullptr, SM_BIAS0,
                     g_c0, g_h0h[wp], g_h0l[wp], nullptr);
        gbarg(bar, target);
        lstm_step<1>(sm, 2,
                     g_h1h[rp], g_h1l[rp], w1,
                     g_h0h[wp], g_h0l[wp], w2,
                     mBase, nt, t, nullptr, nullptr, SM_BIAS1,
                     g_c1, g_h1h[wp], g_h1l[wp], g_enc + (size_t)t * HH);
        gbarg(bar, target);
    }
}

// ---------------- persistent decoder: per-group barriers, 4 phases/step ----------------
__global__ __launch_bounds__(256, 1)
void dec_persist(const float* __restrict__ dWih, const float* __restrict__ db,
                 const float* __restrict__ attW, const float* __restrict__ catW,
                 const float* __restrict__ catb, const float* __restrict__ fcW,
                 const float* __restrict__ fcb, float* __restrict__ out, unsigned* barArr)
{
    extern __shared__ __align__(16) char sm[];
    const int tid = threadIdx.x;
    const int grp = (int)blockIdx.x >> 5;
    const int mBase = grp * 128;
    const int nt = (int)blockIdx.x & 31;
    unsigned* bar = barArr + grp;

    float* bias0 = (float*)(sm + SM_BIAS0);
    float* xw    = (float*)(sm + SM_XW);
    if (tid < 64) {
        int j = tid, row = (j & 3) * 512 + nt * 16 + (j >> 2);
        bias0[j] = __ldg(db + row);
        xw[j] = __ldg(dWih + row);
    }
    __syncthreads();
    const float fcb0 = __ldg(fcb);

    const size_t tsz = (size_t)64 * 512;
    const __half* dw = g_wf + (size_t)(3 * 32 + nt) * tsz;

    unsigned target = 0;
    for (int t = 0; t < TT; t++) {
        const int rp = t & 1, wp = 1 - rp;
        if (nt == 0 && t > 0 && tid < 128)
            out[(size_t)(mBase + tid) * TT + (t - 1)] = __ldcg(&g_pred[mBase + tid]);
        lstm_step<2>(sm, 1,
                     g_h1h[rp], g_h1l[rp], dw,
                     nullptr, nullptr, nullptr,
                     mBase, nt, t, nullptr, g_pred, SM_BIAS0,
                     g_c1, g_h1h[wp], g_h1l[wp], g_hd);
        gbarg(bar, target);
        if (nt == 0 && tid < 128) g_pred[mBase + tid] = fcb0;
        gemm32_tile((float*)(sm + SM_BUF), g_hd, 512, nullptr, 0, attW, 512,
                    nullptr, g_q, 0, nullptr, nullptr);
        gbarg(bar, target);
        attn_phase((float*)(sm + SM_BUF), g_enc, g_q, g_ctx);
        gbarg(bar, target);
        gemm32_tile((float*)(sm + SM_BUF), g_hd, 512, g_ctx, 512, catW, 1024,
                    catb, g_cc, 1, fcW, g_pred);
        gbarg(bar, target);
    }
    if (nt == 0 && tid < 128)
        out[(size_t)(mBase + tid) * TT + (TT - 1)] = __ldcg(&g_pred[mBase + tid]);
}

// ---------------- host ----------------
extern "C" void kernel_launch(void* const* d_in, const int* in_sizes, int n_in,
                              void* d_out, int out_size)
{
    const float* x    = (const float*)d_in[0];
    const float* Wih0 = (const float*)d_in[1];
    const float* Whh0 = (const float*)d_in[2];
    const float* b0   = (const float*)d_in[3];
    const float* Wih1 = (const float*)d_in[4];
    const float* Whh1 = (const float*)d_in[5];
    const float* b1   = (const float*)d_in[6];
    const float* dWih = (const float*)d_in[7];
    const float* dWhh = (const float*)d_in[8];
    const float* db   = (const float*)d_in[9];
    const float* attW = (const float*)d_in[10];
    const float* catW = (const float*)d_in[11];
    const float* catb = (const float*)d_in[12];
    const float* fcW  = (const float*)d_in[13];
    const float* fcb  = (const float*)d_in[14];
    float* out = (float*)d_out;

    static int once = 0;
    if (!once) {
        cudaFuncSetAttribute(enc_persist, cudaFuncAttributeMaxDynamicSharedMemorySize, SMEM_DYN);
        cudaFuncSetAttribute(dec_persist, cudaFuncAttributeMaxDynamicSharedMemorySize, SMEM_DYN);
        once = 1;
    }

    float *c0p, *c1p, *predp;
    __half *h0hp, *h0lp, *h1hp, *h1lp;
    unsigned *barE, *barD;
    cudaGetSymbolAddress((void**)&c0p,  g_c0);
    cudaGetSymbolAddress((void**)&c1p,  g_c1);
    cudaGetSymbolAddress((void**)&predp,g_pred);
    cudaGetSymbolAddress((void**)&h0hp, g_h0h);
    cudaGetSymbolAddress((void**)&h0lp, g_h0l);
    cudaGetSymbolAddress((void**)&h1hp, g_h1h);
    cudaGetSymbolAddress((void**)&h1lp, g_h1l);
    cudaGetSymbolAddress((void**)&barE, g_barE);
    cudaGetSymbolAddress((void**)&barD, g_barD);

    const size_t sf = (size_t)BB * HH * sizeof(float);
    const size_t sh = (size_t)BB * HH * sizeof(__half);
    cudaMemsetAsync(c0p, 0, sf);
    cudaMemsetAsync(c1p, 0, sf);
    cudaMemsetAsync(h0hp, 0, sh);   // parity-0 buffers
    cudaMemsetAsync(h0lp, 0, sh);
    cudaMemsetAsync(h1hp, 0, sh);
    cudaMemsetAsync(h1lp, 0, sh);
    cudaMemsetAsync(barE, 0, 4 * sizeof(unsigned));
    cudaMemsetAsync(barD, 0, 4 * sizeof(unsigned));

    prep_weights<<<1024, 256>>>(Whh0, Whh1, Wih1, dWhh);
    init_pred_kernel<<<2, 256>>>(x, predp);

    enc_persist<<<NCTA, 256, SMEM_DYN>>>(x, Wih0, b0, b1, barE);
    dec_persist<<<NCTA, 256, SMEM_DYN>>>(dWih, db, attW, catW, catb, fcW, fcb, out, barD);
}

// round 13
// speedup vs baseline: 1.4606x; 1.1958x over previous
#include <cuda_runtime.h>
#include <cuda_fp16.h>
#include <cstdint>

#define BB 512
#define SS 336
#define INW 7
#define HH 512
#define TT 96
#define NCTA 128
#define GRP 32    // CTAs per independent group

typedef unsigned long long ull;

// ---------------- smem layout (bytes) ----------------
#define SM_BIAS0 0
#define SM_BIAS1 256
#define SM_XW    512
#define SM_XS    2560
#define SM_BUF   8192
#define OFF_A    0            // 128 rows * 144B = 18432
#define OFF_B    18432        // 64 rows * 144B = 9216
#define BUFSZ    27648
#define SMEM_DYN (SM_BUF + 2 * BUFSZ)   // 63488

// ---------------- device scratch ----------------
__device__ __align__(16) float g_c0 [BB * HH];
__device__ __align__(16) float g_c1 [BB * HH];
__device__ __align__(16) float g_enc[(size_t)BB * SS * HH];   // fp32 encoder out
__device__ __align__(16) float g_q  [BB * HH];
__device__ __align__(16) float g_ctx[BB * HH];
__device__ __align__(16) float g_cc [BB * HH];
__device__ __align__(16) float g_hd [BB * HH];
__device__ __align__(16) float g_pred[BB];
__device__ __align__(16) __half g_h0[2][BB * HH];
__device__ __align__(16) __half g_h1[2][BB * HH];
// reordered weights (fp16): [mat(4)][nt(32)][j(64)][k(512)], j=u*4+g
#define WR_ELEMS ((size_t)4 * 32 * 64 * 512)
__device__ __align__(16) __half g_wf[WR_ELEMS];
__device__ unsigned g_barE[4];
__device__ unsigned g_barD[4];

// ---------------- PTX helpers ----------------
__device__ __forceinline__ uint32_t smem_u32(const void* p) {
    uint32_t a;
    asm("{ .reg .u64 t; cvta.to.shared.u64 t, %1; cvt.u32.u64 %0, t; }" : "=r"(a) : "l"(p));
    return a;
}
__device__ __forceinline__ void cpa_cg(uint32_t s, const void* g) {
    asm volatile("cp.async.cg.shared.global [%0], [%1], 16;" :: "r"(s), "l"(g));
}
__device__ __forceinline__ void cpa_commit() { asm volatile("cp.async.commit_group;"); }
template<int N>
__device__ __forceinline__ void cpa_wait() { asm volatile("cp.async.wait_group %0;" :: "n"(N)); }

__device__ __forceinline__ void ldm4(uint32_t* r, uint32_t a) {
    asm volatile("ldmatrix.sync.aligned.m8n8.x4.shared.b16 {%0,%1,%2,%3}, [%4];"
        : "=r"(r[0]), "=r"(r[1]), "=r"(r[2]), "=r"(r[3]) : "r"(a));
}
__device__ __forceinline__ void mma16816h(float* d, const uint32_t* a, const uint32_t* b) {
    asm volatile("mma.sync.aligned.m16n8k16.row.col.f32.f16.f16.f32 "
        "{%0,%1,%2,%3}, {%4,%5,%6,%7}, {%8,%9}, {%0,%1,%2,%3};"
        : "+f"(d[0]), "+f"(d[1]), "+f"(d[2]), "+f"(d[3])
        : "r"(a[0]), "r"(a[1]), "r"(a[2]), "r"(a[3]), "r"(b[0]), "r"(b[1]));
}

__device__ __forceinline__ ull pack2(float x, float y) {
    ull r; asm("mov.b64 %0, {%1, %2};" : "=l"(r) : "f"(x), "f"(y)); return r;
}
__device__ __forceinline__ float2 unpack2(ull v) {
    float2 r; asm("mov.b64 {%0, %1}, %2;" : "=f"(r.x), "=f"(r.y) : "l"(v)); return r;
}
__device__ __forceinline__ void fma2(ull& d, ull a, ull b) {
    asm("fma.rn.f32x2 %0, %1, %2, %0;" : "+l"(d) : "l"(a), "l"(b));
}

__device__ __forceinline__ float ftanh(float x) {
    return 1.f - 2.f / (__expf(2.f * x) + 1.f);
}

// per-group barrier: 32 CTAs, own counter
__device__ __forceinline__ void gbarg(unsigned* cnt, unsigned& target) {
    __threadfence();
    __syncthreads();
    target += GRP;
    if (threadIdx.x == 0) {
        atomicAdd(cnt, 1u);
        while (*(volatile unsigned*)cnt < target) { }
        __threadfence();
    }
    __syncthreads();
}

// ---------------- MMA LSTM step: K=64 chunks, 2-stage pipeline, single-term fp16 ----------------
__device__ __forceinline__ void load_chunk(uint32_t sbase, int ch,
                                           const __half* A_f, const __half* W_f,
                                           int mBase, int tid)
{
    const int k0 = (ch & 7) * 64;
    const uint32_t sbuf = sbase + SM_BUF + (ch & 1) * BUFSZ;
#pragma unroll
    for (int i = 0; i < 4; i++) {
        int idx = tid + i * 256;
        int row = idx >> 3, cg = idx & 7;
        uint32_t so = row * 144 + cg * 16;
        size_t go = (size_t)(mBase + row) * 512 + k0 + cg * 8;
        cpa_cg(sbuf + OFF_A + so, A_f + go);
    }
#pragma unroll
    for (int i = 0; i < 2; i++) {
        int idx = tid + i * 256;
        int row = idx >> 3, cg = idx & 7;
        uint32_t so = row * 144 + cg * 16;
        size_t go = (size_t)row * 512 + k0 + cg * 8;
        cpa_cg(sbuf + OFF_B + so, W_f + go);
    }
    cpa_commit();
}

__device__ __forceinline__ void compute_chunk(uint32_t sbuf, float acc[2][4][4],
                                              int lane, int wm, int wn)
{
    const int q = lane >> 3, r = lane & 7;
    const uint32_t aOff = (uint32_t)(wm * 32 + (q & 1) * 8 + r) * 144 + ((q >> 1) * 8) * 2;
    const uint32_t bOff = (uint32_t)(wn * 32 + (q >> 1) * 8 + r) * 144 + ((q & 1) * 8) * 2;
    const uint32_t sA = sbuf + OFF_A, sB = sbuf + OFF_B;
#pragma unroll
    for (int ks = 0; ks < 4; ks++) {
        const uint32_t kb = ks * 32;
        uint32_t af[2][4], bf[4][2], t4[4];
        ldm4(af[0], sA + aOff + kb);
        ldm4(af[1], sA + aOff + 16 * 144 + kb);
        ldm4(t4, sB + bOff + kb);
        bf[0][0] = t4[0]; bf[0][1] = t4[1]; bf[1][0] = t4[2]; bf[1][1] = t4[3];
        ldm4(t4, sB + bOff + 16 * 144 + kb);
        bf[2][0] = t4[0]; bf[2][1] = t4[1]; bf[3][0] = t4[2]; bf[3][1] = t4[3];
#pragma unroll
        for (int fm = 0; fm < 2; fm++)
#pragma unroll
            for (int fn = 0; fn < 4; fn++)
                mma16816h(acc[fm][fn], af[fm], bf[fn]);
    }
}

// MODE 0: enc L0 (x tail), MODE 1: enc L1 (fp32 enc out), MODE 2: decoder (+g_hd)
template<int MODE>
__device__ void lstm_step(char* sm, int nmat,
                          const __half* A0, const __half* W0,
                          const __half* A1, const __half* W1,
                          int mBase, int nt, int t,
                          const float* __restrict__ x,
                          const float* __restrict__ pred,
                          int bias_off,
                          float* __restrict__ cst,
                          __half* __restrict__ hO,
                          float* __restrict__ fout)
{
    const int tid = threadIdx.x;
    const int lane = tid & 31, wid = tid >> 5;
    const int wm = wid >> 1, wn = wid & 1;
    const uint32_t sbase = smem_u32(sm);
    float* xs = (float*)(sm + SM_XS);

    if (MODE == 0) {
        for (int idx = tid; idx < 1024; idx += 256) {
            int row = idx >> 3, k = idx & 7;
            if (k < INW)
                xs[idx] = __ldg(x + (size_t)(mBase + row) * (SS * INW) + t * INW + k);
        }
    }
    if (MODE == 2) {
        if (tid < 128) xs[tid] = __ldcg(pred + mBase + tid);
    }

    float acc[2][4][4];
#pragma unroll
    for (int i = 0; i < 2; i++)
#pragma unroll
        for (int j = 0; j < 4; j++)
#pragma unroll
            for (int k = 0; k < 4; k++) acc[i][j][k] = 0.f;

    const int nch = nmat * 8;
    load_chunk(sbase, 0, A0, W0, mBase, tid);
    for (int c = 0; c < nch; c++) {
        if (c + 1 < nch) {
            const int m1 = (c + 1) >> 3;
            load_chunk(sbase, c + 1, m1 ? A1 : A0, m1 ? W1 : W0, mBase, tid);
            cpa_wait<1>();
        } else {
            cpa_wait<0>();
        }
        __syncthreads();
        compute_chunk(sbase + SM_BUF + (c & 1) * BUFSZ, acc, lane, wm, wn);
        __syncthreads();
    }

    const float* bias = (const float*)(sm + bias_off);
    const float* xw = (const float*)(sm + SM_XW);
    const int rr = lane >> 2, cp = lane & 3, p = cp & 1;
#pragma unroll
    for (int fm = 0; fm < 2; fm++)
#pragma unroll
        for (int fn = 0; fn < 4; fn++) {
            float v0 = acc[fm][fn][0], v1 = acc[fm][fn][1];
            float v2 = acc[fm][fn][2], v3 = acc[fm][fn][3];
            float w0 = __shfl_xor_sync(0xffffffffu, v0, 1);
            float w1 = __shfl_xor_sync(0xffffffffu, v1, 1);
            float w2 = __shfl_xor_sync(0xffffffffu, v2, 1);
            float w3 = __shfl_xor_sync(0xffffffffu, v3, 1);
            const int ul = wn * 8 + fn * 2 + (cp >> 1);
            const int b = mBase + wm * 32 + fm * 16 + rr + (p ? 8 : 0);
            float gi, gf, gg, go;
            if (p == 0) { gi = v0; gf = v1; gg = w0; go = w1; }
            else        { gi = w2; gf = w3; gg = v2; go = v3; }
            const int j0 = ul * 4;
            gi += bias[j0 + 0];
            gf += bias[j0 + 1];
            gg += bias[j0 + 2];
            go += bias[j0 + 3];
            if (MODE == 0) {
                const float* xr = xs + (b - mBase) * 8;
#pragma unroll
                for (int k = 0; k < INW; k++) {
                    float xv = xr[k];
                    gi += xv * xw[(j0 + 0) * 8 + k];
                    gf += xv * xw[(j0 + 1) * 8 + k];
                    gg += xv * xw[(j0 + 2) * 8 + k];
                    go += xv * xw[(j0 + 3) * 8 + k];
                }
            }
            if (MODE == 2) {
                float pb = xs[b - mBase];
                gi += pb * xw[j0 + 0];
                gf += pb * xw[j0 + 1];
                gg += pb * xw[j0 + 2];
                go += pb * xw[j0 + 3];
            }
            const int hid = nt * 16 + ul;
            const int idx = b * 512 + hid;
            float si = 1.f / (1.f + __expf(-gi));
            float sf = 1.f / (1.f + __expf(-gf));
            float so = 1.f / (1.f + __expf(-go));
            float cn = sf * cst[idx] + si * ftanh(gg);
            float hn = so * ftanh(cn);
            cst[idx] = cn;
            hO[idx] = __float2half(hn);
            if (MODE == 1) fout[(size_t)b * (SS * HH) + hid] = hn;
            if (MODE == 2) fout[idx] = hn;
        }
}

// ---------------- SIMT decoder pieces (R8/R12 verbatim) ----------------
__device__ void gemm32_tile(float* sm,
                            const float* __restrict__ A1, int K1,
                            const float* __restrict__ A2, int K2,
                            const float* __restrict__ W, int ldw,
                            const float* __restrict__ bias,
                            float* __restrict__ out, int act,
                            const float* __restrict__ fcW, float* __restrict__ predOut)
{
    float (*As)[36] = (float(*)[36])sm;
    float (*Bs)[68] = (float(*)[68])(sm + 16 * 36);
    const int tid = threadIdx.x;
    const int tx = tid & 15, ty = tid >> 4;
    const int mBase = ((int)blockIdx.x >> 3) * 32;
    const int nBase = ((int)blockIdx.x & 7) * 64;
    ull acc2[2][2] = {{0ull, 0ull}, {0ull, 0ull}};
    for (int part = 0; part < 2; part++) {
        const float* A = part ? A2 : A1;
        const int K = part ? K2 : K1;
        const int coff = part ? K1 : 0;
        if (A == nullptr || K == 0) continue;
        for (int k0 = 0; k0 < K; k0 += 16) {
            {   int m = tid >> 3, kc = tid & 7;
                float2 v = __ldcg((const float2*)(A + (size_t)(mBase + m) * K + k0 + kc * 2));
                As[kc * 2 + 0][m] = v.x;
                As[kc * 2 + 1][m] = v.y;
            }
            {   int rr = tid >> 2, kc = tid & 3;
                float4 v = *(const float4*)(W + (size_t)(nBase + rr) * ldw + coff + k0 + kc * 4);
                Bs[kc * 4 + 0][rr] = v.x;
                Bs[kc * 4 + 1][rr] = v.y;
                Bs[kc * 4 + 2][rr] = v.z;
                Bs[kc * 4 + 3][rr] = v.w;
            }
            __syncthreads();
#pragma unroll
            for (int k = 0; k < 16; k++) {
                ull av[2];
#pragma unroll
                for (int i = 0; i < 2; i++) { float a = As[k][ty * 2 + i]; av[i] = pack2(a, a); }
                ull bv0 = *(const ull*)&Bs[k][tx * 4];
                ull bv1 = *(const ull*)&Bs[k][tx * 4 + 2];
#pragma unroll
                for (int i = 0; i < 2; i++) { fma2(acc2[i][0], av[i], bv0); fma2(acc2[i][1], av[i], bv1); }
            }
            __syncthreads();
        }
    }
    float fcp[2] = {0.f, 0.f};
#pragma unroll
    for (int i = 0; i < 2; i++)
#pragma unroll
        for (int jp = 0; jp < 2; jp++) {
            float2 v = unpack2(acc2[i][jp]);
            int row = mBase + ty * 2 + i;
            int col = nBase + tx * 4 + jp * 2;
            float v0 = v.x + (bias ? bias[col] : 0.f);
            float v1 = v.y + (bias ? bias[col + 1] : 0.f);
            if (act) { v0 = ftanh(v0); v1 = ftanh(v1); }
            out[row * 512 + col] = v0;
            out[row * 512 + col + 1] = v1;
            if (fcW) fcp[i] += v0 * __ldg(fcW + col) + v1 * __ldg(fcW + col + 1);
        }
    if (fcW) {
#pragma unroll
        for (int o = 1; o < 16; o <<= 1) {
            fcp[0] += __shfl_xor_sync(0xffffffffu, fcp[0], o);
            fcp[1] += __shfl_xor_sync(0xffffffffu, fcp[1], o);
        }
        if (tx == 0) {
            atomicAdd(&predOut[mBase + ty * 2 + 0], fcp[0]);
            atomicAdd(&predOut[mBase + ty * 2 + 1], fcp[1]);
        }
    }
}

// attention (proven fp32 path)
__device__ void attn_phase(float* sm, const float* __restrict__ enc,
                           const float* __restrict__ q, float* __restrict__ ctx)
{
    float* qs = sm; float* cs = sm + 512; float* ms = sm + 1024; float* ds = sm + 1032;
    const int tid = threadIdx.x, warp = tid >> 5, lane = tid & 31;
    for (int bi = 0; bi < 4; bi++) {
        const int b = (int)blockIdx.x * 4 + bi;
        qs[tid] = __ldcg(&q[b * 512 + tid]);
        qs[tid + 256] = __ldcg(&q[b * 512 + tid + 256]);
        cs[tid] = 0.f; cs[tid + 256] = 0.f;
        __syncthreads();
        float m = -1e30f, d = 0.f;
        float cacc[16];
#pragma unroll
        for (int k = 0; k < 16; k++) cacc[k] = 0.f;
        const float* base = enc + (size_t)b * SS * HH;
        for (int s0 = warp * 2; s0 < SS; s0 += 16) {
            const float* r0 = base + (size_t)s0 * 512;
            const float* r1 = r0 + 512;
            float4 v0[4], v1[4];
            float p0 = 0.f, p1 = 0.f;
#pragma unroll
            for (int ch = 0; ch < 4; ch++) {
                v0[ch] = __ldcs((const float4*)(r0 + ch * 128 + lane * 4));
                v1[ch] = __ldcs((const float4*)(r1 + ch * 128 + lane * 4));
            }
#pragma unroll
            for (int ch = 0; ch < 4; ch++) {
                float4 qv = *(const float4*)(qs + ch * 128 + lane * 4);
                p0 += v0[ch].x * qv.x + v0[ch].y * qv.y + v0[ch].z * qv.z + v0[ch].w * qv.w;
                p1 += v1[ch].x * qv.x + v1[ch].y * qv.y + v1[ch].z * qv.z + v1[ch].w * qv.w;
            }
#pragma unroll
            for (int o = 16; o; o >>= 1) {
                p0 += __shfl_xor_sync(0xffffffffu, p0, o);
                p1 += __shfl_xor_sync(0xffffffffu, p1, o);
            }
            {   float mn = fmaxf(m, p0);
                float sc = __expf(m - mn), w = __expf(p0 - mn);
                d = d * sc + w;
#pragma unroll
                for (int ch = 0; ch < 4; ch++) {
                    cacc[ch*4+0] = cacc[ch*4+0]*sc + w*v0[ch].x;
                    cacc[ch*4+1] = cacc[ch*4+1]*sc + w*v0[ch].y;
                    cacc[ch*4+2] = cacc[ch*4+2]*sc + w*v0[ch].z;
                    cacc[ch*4+3] = cacc[ch*4+3]*sc + w*v0[ch].w;
                }
                m = mn;
            }
            {   float mn = fmaxf(m, p1);
                float sc = __expf(m - mn), w = __expf(p1 - mn);
                d = d * sc + w;
#pragma unroll
                for (int ch = 0; ch < 4; ch++) {
                    cacc[ch*4+0] = cacc[ch*4+0]*sc + w*v1[ch].x;
                    cacc[ch*4+1] = cacc[ch*4+1]*sc + w*v1[ch].y;
                    cacc[ch*4+2] = cacc[ch*4+2]*sc + w*v1[ch].z;
                    cacc[ch*4+3] = cacc[ch*4+3]*sc + w*v1[ch].w;
                }
                m = mn;
            }
        }
        if (lane == 0) { ms[warp] = m; ds[warp] = d; }
        __syncthreads();
        float M = -1e30f;
#pragma unroll
        for (int w8 = 0; w8 < 8; w8++) M = fmaxf(M, ms[w8]);
        float D = 0.f;
#pragma unroll
        for (int w8 = 0; w8 < 8; w8++) D += ds[w8] * __expf(ms[w8] - M);
        float f = __expf(m - M);
#pragma unroll
        for (int ch = 0; ch < 4; ch++) {
            atomicAdd(&cs[ch*128 + lane*4 + 0], cacc[ch*4+0] * f);
            atomicAdd(&cs[ch*128 + lane*4 + 1], cacc[ch*4+1] * f);
            atomicAdd(&cs[ch*128 + lane*4 + 2], cacc[ch*4+2] * f);
            atomicAdd(&cs[ch*128 + lane*4 + 3], cacc[ch*4+3] * f);
        }
        __syncthreads();
        float invD = 1.f / D;
        ctx[b * 512 + tid] = cs[tid] * invD;
        ctx[b * 512 + tid + 256] = cs[tid + 256] * invD;
        __syncthreads();
    }
}

// ---------------- prep kernels ----------------
__global__ void prep_weights(const float* __restrict__ Whh0, const float* __restrict__ Whh1,
                             const float* __restrict__ Wih1, const float* __restrict__ dWhh)
{
    const float* mats[4] = {Whh0, Whh1, Wih1, dWhh};
    for (size_t i = (size_t)blockIdx.x * 256 + threadIdx.x; i < WR_ELEMS;
         i += (size_t)gridDim.x * 256) {
        int k  = (int)(i & 511);
        int j  = (int)((i >> 9) & 63);
        int nt = (int)((i >> 15) & 31);
        int m  = (int)(i >> 20);
        int row = (j & 3) * 512 + nt * 16 + (j >> 2);
        g_wf[i] = __float2half(__ldg(mats[m] + (size_t)row * 512 + k));
    }
}

__global__ void init_pred_kernel(const float* __restrict__ x, float* __restrict__ pred)
{
    int b = blockIdx.x * 256 + threadIdx.x;
    if (b < BB) pred[b] = x[(size_t)b * (SS * INW) + (SS - 1) * INW + (INW - 1)];
}

// ---------------- persistent encoder: per-group barriers ----------------
__global__ __launch_bounds__(256, 1)
void enc_persist(const float* __restrict__ x, const float* __restrict__ Wih0,
                 const float* __restrict__ b0, const float* __restrict__ b1,
                 unsigned* barArr)
{
    extern __shared__ __align__(16) char sm[];
    const int tid = threadIdx.x;
    const int grp = (int)blockIdx.x >> 5;
    const int mBase = grp * 128;
    const int nt = (int)blockIdx.x & 31;
    unsigned* bar = barArr + grp;

    float* bias0 = (float*)(sm + SM_BIAS0);
    float* bias1 = (float*)(sm + SM_BIAS1);
    float* xw    = (float*)(sm + SM_XW);
    if (tid < 64) {
        int j = tid, row = (j & 3) * 512 + nt * 16 + (j >> 2);
        bias0[j] = __ldg(b0 + row);
        bias1[j] = __ldg(b1 + row);
        for (int k = 0; k < INW; k++) xw[j * 8 + k] = __ldg(Wih0 + (size_t)row * INW + k);
    }
    __syncthreads();

    const size_t tsz = (size_t)64 * 512;
    const __half* w0 = g_wf + (size_t)(0 * 32 + nt) * tsz;
    const __half* w1 = g_wf + (size_t)(1 * 32 + nt) * tsz;
    const __half* w2 = g_wf + (size_t)(2 * 32 + nt) * tsz;

    unsigned target = 0;
    for (int t = 0; t < SS; t++) {
        const int rp = t & 1, wp = 1 - rp;
        lstm_step<0>(sm, 1,
                     g_h0[rp], w0, nullptr, nullptr,
                     mBase, nt, t, x, nullptr, SM_BIAS0,
                     g_c0, g_h0[wp], nullptr);
        gbarg(bar, target);
        lstm_step<1>(sm, 2,
                     g_h1[rp], w1, g_h0[wp], w2,
                     mBase, nt, t, nullptr, nullptr, SM_BIAS1,
                     g_c1, g_h1[wp], g_enc + (size_t)t * HH);
        gbarg(bar, target);
    }
}

// ---------------- persistent decoder: per-group barriers, 4 phases/step ----------------
__global__ __launch_bounds__(256, 1)
void dec_persist(const float* __restrict__ dWih, const float* __restrict__ db,
                 const float* __restrict__ attW, const float* __restrict__ catW,
                 const float* __restrict__ catb, const float* __restrict__ fcW,
                 const float* __restrict__ fcb, float* __restrict__ out, unsigned* barArr)
{
    extern __shared__ __align__(16) char sm[];
    const int tid = threadIdx.x;
    const int grp = (int)blockIdx.x >> 5;
    const int mBase = grp * 128;
    const int nt = (int)blockIdx.x & 31;
    unsigned* bar = barArr + grp;

    float* bias0 = (float*)(sm + SM_BIAS0);
    float* xw    = (float*)(sm + SM_XW);
    if (tid < 64) {
        int j = tid, row = (j & 3) * 512 + nt * 16 + (j >> 2);
        bias0[j] = __ldg(db + row);
        xw[j] = __ldg(dWih + row);
    }
    __syncthreads();
    const float fcb0 = __ldg(fcb);

    const size_t tsz = (size_t)64 * 512;
    const __half* dw = g_wf + (size_t)(3 * 32 + nt) * tsz;

    unsigned target = 0;
    for (int t = 0; t < TT; t++) {
        const int rp = t & 1, wp = 1 - rp;
        if (nt == 0 && t > 0 && tid < 128)
            out[(size_t)(mBase + tid) * TT + (t - 1)] = __ldcg(&g_pred[mBase + tid]);
        lstm_step<2>(sm, 1,
                     g_h1[rp], dw, nullptr, nullptr,
                     mBase, nt, t, nullptr, g_pred, SM_BIAS0,
                     g_c1, g_h1[wp], g_hd);
        gbarg(bar, target);
        if (nt == 0 && tid < 128) g_pred[mBase + tid] = fcb0;
        gemm32_tile((float*)(sm + SM_BUF), g_hd, 512, nullptr, 0, attW, 512,
                    nullptr, g_q, 0, nullptr, nullptr);
        gbarg(bar, target);
        attn_phase((float*)(sm + SM_BUF), g_enc, g_q, g_ctx);
        gbarg(bar, target);
        gemm32_tile((float*)(sm + SM_BUF), g_hd, 512, g_ctx, 512, catW, 1024,
                    catb, g_cc, 1, fcW, g_pred);
        gbarg(bar, target);
    }
    if (nt == 0 && tid < 128)
        out[(size_t)(mBase + tid) * TT + (TT - 1)] = __ldcg(&g_pred[mBase + tid]);
}

// ---------------- host ----------------
extern "C" void kernel_launch(void* const* d_in, const int* in_sizes, int n_in,
                              void* d_out, int out_size)
{
    const float* x    = (const float*)d_in[0];
    const float* Wih0 = (const float*)d_in[1];
    const float* Whh0 = (const float*)d_in[2];
    const float* b0   = (const float*)d_in[3];
    const float* Wih1 = (const float*)d_in[4];
    const float* Whh1 = (const float*)d_in[5];
    const float* b1   = (const float*)d_in[6];
    const float* dWih = (const float*)d_in[7];
    const float* dWhh = (const float*)d_in[8];
    const float* db   = (const float*)d_in[9];
    const float* attW = (const float*)d_in[10];
    const float* catW = (const float*)d_in[11];
    const float* catb = (const float*)d_in[12];
    const float* fcW  = (const float*)d_in[13];
    const float* fcb  = (const float*)d_in[14];
    float* out = (float*)d_out;

    static int once = 0;
    if (!once) {
        cudaFuncSetAttribute(enc_persist, cudaFuncAttributeMaxDynamicSharedMemorySize, SMEM_DYN);
        cudaFuncSetAttribute(dec_persist, cudaFuncAttributeMaxDynamicSharedMemorySize, SMEM_DYN);
        once = 1;
    }

    float *c0p, *c1p, *predp;
    __half *h0p, *h1p;
    unsigned *barE, *barD;
    cudaGetSymbolAddress((void**)&c0p,  g_c0);
    cudaGetSymbolAddress((void**)&c1p,  g_c1);
    cudaGetSymbolAddress((void**)&predp,g_pred);
    cudaGetSymbolAddress((void**)&h0p,  g_h0);
    cudaGetSymbolAddress((void**)&h1p,  g_h1);
    cudaGetSymbolAddress((void**)&barE, g_barE);
    cudaGetSymbolAddress((void**)&barD, g_barD);

    const size_t sf = (size_t)BB * HH * sizeof(float);
    const size_t sh = (size_t)BB * HH * sizeof(__half);
    cudaMemsetAsync(c0p, 0, sf);
    cudaMemsetAsync(c1p, 0, sf);
    cudaMemsetAsync(h0p, 0, sh);   // parity-0 buffers
    cudaMemsetAsync(h1p, 0, sh);
    cudaMemsetAsync(barE, 0, 4 * sizeof(unsigned));
    cudaMemsetAsync(barD, 0, 4 * sizeof(unsigned));

    prep_weights<<<1024, 256>>>(Whh0, Whh1, Wih1, dWhh);
    init_pred_kernel<<<2, 256>>>(x, predp);

    enc_persist<<<NCTA, 256, SMEM_DYN>>>(x, Wih0, b0, b1, barE);
    dec_persist<<<NCTA, 256, SMEM_DYN>>>(dWih, db, attW, catW, catb, fcW, fcb, out, barD);
}